// round 2
// baseline (speedup 1.0000x reference)
#include <cuda_runtime.h>
#include <math.h>

#define LL 512
#define BB 64
#define EE 256
#define HH 256
#define HID 512
#define NG 1024      // 4*H gate rows
#define CC 5
#define TAG_START 3
#define TAG_STOP 4
#define IMPOSSIBLE_F (-1e4f)

// ---------------- scratch (device globals; no cudaMalloc allowed) -------------
__device__ float g_embx [(size_t)LL * BB * EE];        //  33.5 MB  layer-0 input  [t][b][e]
__device__ float g_bufA [(size_t)LL * BB * HID];       //  67 MB    layer output   [t][b][512]
__device__ float g_bufB [(size_t)LL * BB * HID];       //  67 MB
__device__ float g_gates[(size_t)2 * LL * BB * NG];    // 268 MB    input-proj gates [dir][t][b][1024]
__device__ float g_emit [(size_t)LL * BB * CC];        //  emissions [t][b][c]
__device__ int   g_bp   [(size_t)LL * BB * CC];        //  backpointers
__device__ unsigned g_bar;                             //  grid barrier counter

__global__ void init_bar_k() { if (threadIdx.x == 0) g_bar = 0u; }

// ---------------- embedding gather: X[t][b][:] = emb[xs[b][t]] ----------------
__global__ void embed_k(const int* __restrict__ xs, const float* __restrict__ emb,
                        float* __restrict__ X)
{
    size_t i = (size_t)blockIdx.x * blockDim.x + threadIdx.x;   // float4 units
    size_t total = (size_t)LL * BB * (EE / 4);
    if (i >= total) return;
    int e4 = (int)(i % (EE / 4));
    size_t p = i / (EE / 4);               // p = t*64 + b
    int b = (int)(p % BB);
    int t = (int)(p / BB);
    int tok = xs[(size_t)b * LL + t];
    *(float4*)&X[p * EE + e4 * 4] = *(const float4*)&emb[(size_t)tok * EE + e4 * 4];
}

// ---------------- input-projection GEMM: G[dir][m][n] = A[m,:]·W[dir][n,:] + bias[n]
__global__ __launch_bounds__(256) void gemm_in_k(
    const float* __restrict__ A,
    const float* __restrict__ W0, const float* __restrict__ W1,
    const float* __restrict__ bias0, const float* __restrict__ bias1,
    float* __restrict__ G, int K)
{
    const int M = LL * BB;
    int dir = blockIdx.z;
    const float* W    = dir ? W1 : W0;
    const float* bias = dir ? bias1 : bias0;
    float* Gout = G + (size_t)dir * M * NG;

    __shared__ float As[8][128];
    __shared__ float Bs[8][128];

    int tid = threadIdx.x;
    int m0 = blockIdx.x * 128, n0 = blockIdx.y * 128;
    int tr = tid >> 4, tc = tid & 15;          // 16x16 thread grid, 8x8 micro-tile
    int lrow = tid >> 1, lcol = (tid & 1) << 2;

    float acc[8][8];
#pragma unroll
    for (int i = 0; i < 8; i++)
#pragma unroll
        for (int j = 0; j < 8; j++) acc[i][j] = 0.f;

    const float* Ap = A + (size_t)(m0 + lrow) * K + lcol;
    const float* Wp = W + (size_t)(n0 + lrow) * K + lcol;

    for (int k0 = 0; k0 < K; k0 += 8) {
        float4 av = *(const float4*)(Ap + k0);
        float4 wv = *(const float4*)(Wp + k0);
        As[lcol + 0][lrow] = av.x; As[lcol + 1][lrow] = av.y;
        As[lcol + 2][lrow] = av.z; As[lcol + 3][lrow] = av.w;
        Bs[lcol + 0][lrow] = wv.x; Bs[lcol + 1][lrow] = wv.y;
        Bs[lcol + 2][lrow] = wv.z; Bs[lcol + 3][lrow] = wv.w;
        __syncthreads();
#pragma unroll
        for (int kk = 0; kk < 8; kk++) {
            float a[8], bb[8];
            *(float4*)&a[0]  = *(const float4*)&As[kk][tr * 8];
            *(float4*)&a[4]  = *(const float4*)&As[kk][tr * 8 + 4];
            *(float4*)&bb[0] = *(const float4*)&Bs[kk][tc * 8];
            *(float4*)&bb[4] = *(const float4*)&Bs[kk][tc * 8 + 4];
#pragma unroll
            for (int i = 0; i < 8; i++)
#pragma unroll
                for (int j = 0; j < 8; j++) acc[i][j] += a[i] * bb[j];
        }
        __syncthreads();
    }
#pragma unroll
    for (int i = 0; i < 8; i++) {
        int m = m0 + tr * 8 + i;
#pragma unroll
        for (int j = 0; j < 8; j++) {
            int n = n0 + tc * 8 + j;
            Gout[(size_t)m * NG + n] = acc[i][j] + bias[n];
        }
    }
}

// ---------------- persistent per-layer LSTM recurrence ------------------------
// grid = 128 CTAs (dir = bx>>6, jt = bx&63 -> units j0..j0+3), 256 threads.
// Lane mapping: warp w (0..7), half = lane>>4, r = lane&15 = jj*4 + g.
// Thread accumulates gate-row r for b = 2w + half + 16*rep (rep 0..3).
// c lives in registers of g==0 lanes. One grid barrier per step.
#define HS_STRIDE 260
__global__ __launch_bounds__(256) void lstm_layer_k(
    const float* __restrict__ G,
    const float* __restrict__ Whh0, const float* __restrict__ Whh1,
    float* __restrict__ y, unsigned bar_base)
{
    extern __shared__ float sm[];
    float* hs = sm;                       // [64][HS_STRIDE]
    float* ws = sm + 64 * HS_STRIDE;      // [16][HS_STRIDE]

    int bx  = blockIdx.x;
    int dir = bx >> 6;
    int j0  = (bx & 63) * 4;
    const float* Whh = dir ? Whh1 : Whh0;
    int tid  = threadIdx.x;
    int lane = tid & 31, w = tid >> 5;
    int half = lane >> 4, r = lane & 15;
    int jj = r >> 2, g = r & 3;
    int j  = j0 + jj;
    int bb0 = w * 2 + half;               // +16*rep

    // stage Whh rows once: row r=jj*4+g <- Whh[(g*256 + j0+jj)][:]
#pragma unroll
    for (int u = 0; u < 4; u++) {
        int f  = tid + u * 256;           // float4 index, 1024 total
        int rr = f >> 6;
        int kk = (f & 63) * 4;
        int gg = rr & 3, jq = rr >> 2;
        *(float4*)&ws[rr * HS_STRIDE + kk] =
            *(const float4*)&Whh[(size_t)(gg * 256 + j0 + jq) * HH + kk];
    }

    const float* wrow = &ws[r * HS_STRIDE];
    float cr0 = 0.f, cr1 = 0.f, cr2 = 0.f, cr3 = 0.f;   // cell state (g==0 lanes)
    volatile unsigned* vb = &g_bar;

    for (int s = 0; s < LL; s++) {
        int t     = dir ? (LL - 1 - s) : s;
        int tprev = dir ? (t + 1) : (t - 1);

        // prefetch the 4 input-projection gate values (one per rep)
        size_t gb = ((size_t)dir * LL + t) * BB;
        size_t gof = (size_t)g * 256 + j;
        float a0 = G[(gb + bb0 +  0) * NG + gof];
        float a1 = G[(gb + bb0 + 16) * NG + gof];
        float a2 = G[(gb + bb0 + 32) * NG + gof];
        float a3 = G[(gb + bb0 + 48) * NG + gof];

        if (s > 0) {
            // stage h_prev: warp iter i covers segment seg = i*8+w (128 segs x 512B)
            const float* ybase = y + ((size_t)tprev * BB) * HID + dir * HH;
#pragma unroll
            for (int i = 0; i < 16; i++) {
                int seg = i * 8 + w;
                int sb = seg >> 1, sh = (seg & 1) * 128;
                *(float4*)&hs[sb * HS_STRIDE + sh + lane * 4] =
                    *(const float4*)&ybase[(size_t)sb * HID + sh + lane * 4];
            }
            __syncthreads();

            const float* h0 = &hs[(bb0 +  0) * HS_STRIDE];
            const float* h1 = &hs[(bb0 + 16) * HS_STRIDE];
            const float* h2 = &hs[(bb0 + 32) * HS_STRIDE];
            const float* h3 = &hs[(bb0 + 48) * HS_STRIDE];
#pragma unroll 4
            for (int k = 0; k < HH; k += 4) {
                float4 wv = *(const float4*)&wrow[k];
                float4 v0 = *(const float4*)&h0[k];
                float4 v1 = *(const float4*)&h1[k];
                float4 v2 = *(const float4*)&h2[k];
                float4 v3 = *(const float4*)&h3[k];
                a0 += wv.x * v0.x + wv.y * v0.y + wv.z * v0.z + wv.w * v0.w;
                a1 += wv.x * v1.x + wv.y * v1.y + wv.z * v1.z + wv.w * v1.w;
                a2 += wv.x * v2.x + wv.y * v2.y + wv.z * v2.z + wv.w * v2.w;
                a3 += wv.x * v3.x + wv.y * v3.y + wv.z * v3.z + wv.w * v3.w;
            }
        } else {
            __syncthreads();
        }

        // combine gates i,f,g,o (lanes r = jj*4 + {0,1,2,3}) on g==0 lanes
        float f0 = __shfl_down_sync(0xffffffffu, a0, 1);
        float q0 = __shfl_down_sync(0xffffffffu, a0, 2);
        float o0 = __shfl_down_sync(0xffffffffu, a0, 3);
        float f1 = __shfl_down_sync(0xffffffffu, a1, 1);
        float q1 = __shfl_down_sync(0xffffffffu, a1, 2);
        float o1 = __shfl_down_sync(0xffffffffu, a1, 3);
        float f2 = __shfl_down_sync(0xffffffffu, a2, 1);
        float q2 = __shfl_down_sync(0xffffffffu, a2, 2);
        float o2 = __shfl_down_sync(0xffffffffu, a2, 3);
        float f3 = __shfl_down_sync(0xffffffffu, a3, 1);
        float q3 = __shfl_down_sync(0xffffffffu, a3, 2);
        float o3 = __shfl_down_sync(0xffffffffu, a3, 3);

        if (g == 0) {
            float* yt = y + ((size_t)t * BB) * HID + dir * HH + j;
            float ig, fg, gg2, og;
            ig = 1.f / (1.f + expf(-a0)); fg = 1.f / (1.f + expf(-f0));
            gg2 = tanhf(q0);              og = 1.f / (1.f + expf(-o0));
            cr0 = fg * cr0 + ig * gg2;
            yt[(size_t)(bb0 +  0) * HID] = og * tanhf(cr0);
            ig = 1.f / (1.f + expf(-a1)); fg = 1.f / (1.f + expf(-f1));
            gg2 = tanhf(q1);              og = 1.f / (1.f + expf(-o1));
            cr1 = fg * cr1 + ig * gg2;
            yt[(size_t)(bb0 + 16) * HID] = og * tanhf(cr1);
            ig = 1.f / (1.f + expf(-a2)); fg = 1.f / (1.f + expf(-f2));
            gg2 = tanhf(q2);              og = 1.f / (1.f + expf(-o2));
            cr2 = fg * cr2 + ig * gg2;
            yt[(size_t)(bb0 + 32) * HID] = og * tanhf(cr2);
            ig = 1.f / (1.f + expf(-a3)); fg = 1.f / (1.f + expf(-f3));
            gg2 = tanhf(q3);              og = 1.f / (1.f + expf(-o3));
            cr3 = fg * cr3 + ig * gg2;
            yt[(size_t)(bb0 + 48) * HID] = og * tanhf(cr3);
        }

        // grid barrier: publish y[t], wait for all 128 CTAs
        __threadfence();
        __syncthreads();
        if (tid == 0) {
            atomicAdd(&g_bar, 1u);
            unsigned target = bar_base + (unsigned)(s + 1) * 128u;
            while (*vb < target) __nanosleep(64);
        }
        __syncthreads();
        __threadfence();
    }
}

// ---------------- FC: emit[t][b][c] = feat[t][b][:]·Wfc[c] + bfc[c] -----------
__global__ void fc_k(const float* __restrict__ feat, const float* __restrict__ Wfc,
                     const float* __restrict__ bfc, float* __restrict__ emit)
{
    int gw = (int)(((size_t)blockIdx.x * blockDim.x + threadIdx.x) >> 5);
    int lane = threadIdx.x & 31;
    if (gw >= LL * BB) return;
    const float* f = feat + (size_t)gw * HID;
    float acc[CC] = {0.f, 0.f, 0.f, 0.f, 0.f};
#pragma unroll
    for (int i = 0; i < HID / 32; i++) {
        int k = lane + i * 32;
        float fv = f[k];
#pragma unroll
        for (int cc = 0; cc < CC; cc++) acc[cc] += fv * Wfc[cc * HID + k];
    }
#pragma unroll
    for (int off = 16; off > 0; off >>= 1)
#pragma unroll
        for (int cc = 0; cc < CC; cc++)
            acc[cc] += __shfl_down_sync(0xffffffffu, acc[cc], off);
    if (lane == 0)
#pragma unroll
        for (int cc = 0; cc < CC; cc++)
            emit[(size_t)gw * CC + cc] = acc[cc] + bfc[cc];
}

// ---------------- Viterbi + backtrace, one warp per batch element -------------
__global__ void viterbi_k(const float* __restrict__ emit, const float* __restrict__ trans,
                          int* __restrict__ bp, float* __restrict__ out, long long osz)
{
    int b = blockIdx.x;
    int lane = threadIdx.x;
    float tr[CC];
    if (lane < CC)
#pragma unroll
        for (int f = 0; f < CC; f++) tr[f] = trans[lane * CC + f];
    float score = (lane == TAG_START) ? 0.f : IMPOSSIBLE_F;

    for (int t = 0; t < LL; t++) {
        float sc[CC];
#pragma unroll
        for (int f = 0; f < CC; f++) sc[f] = __shfl_sync(0xffffffffu, score, f);
        if (lane < CC) {
            float best = sc[0] + tr[0];
            int arg = 0;
#pragma unroll
            for (int f = 1; f < CC; f++) {
                float v = sc[f] + tr[f];
                if (v > best) { best = v; arg = f; }
            }
            bp[((size_t)t * BB + b) * CC + lane] = arg;
            score = best + emit[((size_t)t * BB + b) * CC + lane];
        }
    }
    if (lane < CC) score += trans[TAG_STOP * CC + lane];
    float sc[CC];
#pragma unroll
    for (int f = 0; f < CC; f++) sc[f] = __shfl_sync(0xffffffffu, score, f);
    if (lane == 0) {
        float best = sc[0];
        int tag = 0;
#pragma unroll
        for (int f = 1; f < CC; f++)
            if (sc[f] > best) { best = sc[f]; tag = f; }
        if (b < osz) out[b] = best;                                   // best_score
        long long tb = 64;                                            // tag_seq base
        long long o = tb + (long long)b * LL + (LL - 1);
        if (o < osz) out[o] = (float)tag;
        for (int t = LL - 1; t >= 1; t--) {
            tag = bp[((size_t)t * BB + b) * CC + tag];
            o = tb + (long long)b * LL + (t - 1);
            if (o < osz) out[o] = (float)tag;
        }
    }
}

// ---------------- features [t][b][k] -> out [b][t][k] -------------------------
__global__ void feat_out_k(const float* __restrict__ feat, float* __restrict__ out,
                           long long osz)
{
    size_t i = (size_t)blockIdx.x * blockDim.x + threadIdx.x;   // float4 units
    size_t total = (size_t)LL * BB * HID / 4;
    if (i >= total) return;
    int k4 = (int)(i % (HID / 4));
    size_t p = i / (HID / 4);        // p = t*64 + b
    int b = (int)(p % BB);
    int t = (int)(p / BB);
    long long o = 32832LL + ((long long)b * LL + t) * HID + k4 * 4;
    if (o + 3 < osz)
        *(float4*)&out[o] = *(const float4*)&feat[p * HID + k4 * 4];
}

__global__ void mask_out_k(float* __restrict__ out, long long osz)
{
    long long i = (long long)blockIdx.x * blockDim.x + threadIdx.x;
    if (i >= (long long)BB * LL) return;
    long long o = 16810048LL + i;    // 64 + 32768 + 64*512*512
    if (o < osz) out[o] = 1.0f;      // all tokens > 0 => masks all True
}

// ---------------- launch -------------------------------------------------------
extern "C" void kernel_launch(void* const* d_in, const int* in_sizes, int n_in,
                              void* d_out, int out_size)
{
    const int*   xs    = (const int*)  d_in[0];
    const float* emb   = (const float*)d_in[1];
    const float* Wih0  = (const float*)d_in[2];   // [2,1024,256]
    const float* Whh0  = (const float*)d_in[3];   // [2,1024,256]
    const float* b0    = (const float*)d_in[4];   // [2,1024]
    const float* WihL  = (const float*)d_in[5];   // [3,2,1024,512]
    const float* WhhL  = (const float*)d_in[6];   // [3,2,1024,256]
    const float* bL    = (const float*)d_in[7];   // [3,2,1024]
    const float* Wfc   = (const float*)d_in[8];   // [5,512]
    const float* bfc   = (const float*)d_in[9];   // [5]
    const float* trans = (const float*)d_in[10];  // [5,5]
    float* out = (float*)d_out;
    long long osz = out_size;

    float *pX, *pA, *pB, *pG, *pE;
    int* pBP;
    cudaGetSymbolAddress((void**)&pX,  g_embx);
    cudaGetSymbolAddress((void**)&pA,  g_bufA);
    cudaGetSymbolAddress((void**)&pB,  g_bufB);
    cudaGetSymbolAddress((void**)&pG,  g_gates);
    cudaGetSymbolAddress((void**)&pE,  g_emit);
    cudaGetSymbolAddress((void**)&pBP, g_bp);

    const int STEP_SMEM = (64 + 16) * HS_STRIDE * 4;   // 83200 bytes
    cudaFuncSetAttribute(lstm_layer_k, cudaFuncAttributeMaxDynamicSharedMemorySize,
                         STEP_SMEM);

    init_bar_k<<<1, 32>>>();

    {
        size_t total = (size_t)LL * BB * (EE / 4);
        embed_k<<<(unsigned)((total + 255) / 256), 256>>>(xs, emb, pX);
    }

    const float* x = pX;
    int K = EE;
    for (int l = 0; l < 4; l++) {
        const float *WihF, *WihB, *WhhF, *WhhB, *bF, *bBk;
        if (l == 0) {
            WihF = Wih0;                 WihB = Wih0 + (size_t)NG * EE;
            WhhF = Whh0;                 WhhB = Whh0 + (size_t)NG * HH;
            bF   = b0;                   bBk  = b0 + NG;
        } else {
            size_t base = (size_t)(l - 1) * 2;
            WihF = WihL + base * NG * HID;       WihB = WihL + (base + 1) * NG * HID;
            WhhF = WhhL + base * NG * HH;        WhhB = WhhL + (base + 1) * NG * HH;
            bF   = bL + base * NG;               bBk  = bL + (base + 1) * NG;
        }
        float* y = (l & 1) ? pB : pA;

        dim3 ggrid(LL * BB / 128, NG / 128, 2);
        gemm_in_k<<<ggrid, 256>>>(x, WihF, WihB, bF, bBk, pG, K);

        lstm_layer_k<<<128, 256, STEP_SMEM>>>(pG, WhhF, WhhB, y,
                                              (unsigned)(l * LL * 128));

        x = y;
        K = HID;
    }

    // x == pB (final features, [t][b][512])
    fc_k<<<(LL * BB * 32) / 256, 256>>>(x, Wfc, bfc, pE);
    viterbi_k<<<BB, 32>>>(pE, trans, pBP, out, osz);
    {
        size_t total = (size_t)LL * BB * HID / 4;
        feat_out_k<<<(unsigned)((total + 255) / 256), 256>>>(x, out, osz);
    }
    mask_out_k<<<(BB * LL + 255) / 256, 256>>>(out, osz);
}

// round 3
// speedup vs baseline: 1.7794x; 1.7794x over previous
#include <cuda_runtime.h>
#include <math.h>

#define LL 512
#define BB 64
#define EE 256
#define HH 256
#define HID 512
#define NG 1024      // 4*H gate rows
#define CC 5
#define TAG_START 3
#define TAG_STOP 4
#define IMPOSSIBLE_F (-1e4f)

typedef unsigned long long ull;

// packed fp32x2 FMA helpers (SASS FFMA2; only reachable via PTX)
__device__ __forceinline__ void fma2(ull& acc, ull a, ull b) {
    asm("fma.rn.f32x2 %0, %1, %2, %0;" : "+l"(acc) : "l"(a), "l"(b));
}
__device__ __forceinline__ ull pk2(float x, float y) {
    ull r; asm("mov.b64 %0, {%1, %2};" : "=l"(r) : "f"(x), "f"(y)); return r;
}
__device__ __forceinline__ float red2(ull v) {
    float x, y; asm("mov.b64 {%0, %1}, %2;" : "=f"(x), "=f"(y) : "l"(v)); return x + y;
}
__device__ __forceinline__ float2 un2(ull v) {
    float x, y; asm("mov.b64 {%0, %1}, %2;" : "=f"(x), "=f"(y) : "l"(v));
    return make_float2(x, y);
}

// ---------------- scratch (device globals; no cudaMalloc allowed) -------------
__device__ float g_embx [(size_t)LL * BB * EE];
__device__ float g_bufA [(size_t)LL * BB * HID];
__device__ float g_bufB [(size_t)LL * BB * HID];
__device__ float g_gates[(size_t)2 * LL * BB * NG];
__device__ float g_emit [(size_t)LL * BB * CC];
__device__ int   g_bp   [(size_t)LL * BB * CC];
__device__ unsigned g_bar2[2];                        // per-direction barrier counters

__global__ void init_bar_k() { if (threadIdx.x < 2) g_bar2[threadIdx.x] = 0u; }

// ---------------- embedding gather: X[t][b][:] = emb[xs[b][t]] ----------------
__global__ void embed_k(const int* __restrict__ xs, const float* __restrict__ emb,
                        float* __restrict__ X)
{
    size_t i = (size_t)blockIdx.x * blockDim.x + threadIdx.x;   // float4 units
    size_t total = (size_t)LL * BB * (EE / 4);
    if (i >= total) return;
    int e4 = (int)(i % (EE / 4));
    size_t p = i / (EE / 4);               // p = t*64 + b
    int b = (int)(p % BB);
    int t = (int)(p / BB);
    int tok = xs[(size_t)b * LL + t];
    *(float4*)&X[p * EE + e4 * 4] = *(const float4*)&emb[(size_t)tok * EE + e4 * 4];
}

// ---------------- input-projection GEMM (double-buffered, FFMA2) --------------
// G[dir][m][n] = A[m,:]·W[dir][n,:] + bias[n].  128x128x8 tile, 8x8/thread.
__global__ __launch_bounds__(256) void gemm_in_k(
    const float* __restrict__ A,
    const float* __restrict__ W0, const float* __restrict__ W1,
    const float* __restrict__ bias0, const float* __restrict__ bias1,
    float* __restrict__ G, int K)
{
    const int M = LL * BB;
    int dir = blockIdx.z;
    const float* W    = dir ? W1 : W0;
    const float* bias = dir ? bias1 : bias0;
    float* Gout = G + (size_t)dir * M * NG;

    __shared__ float As[2][8][128];
    __shared__ float Bs[2][8][128];

    int tid = threadIdx.x;
    int m0 = blockIdx.x * 128, n0 = blockIdx.y * 128;
    int tr = tid >> 4, tc = tid & 15;
    int lrow = tid >> 1, lcol = (tid & 1) << 2;

    ull acc[8][4];
#pragma unroll
    for (int i = 0; i < 8; i++)
#pragma unroll
        for (int j = 0; j < 4; j++) acc[i][j] = pk2(0.f, 0.f);

    const float* Ap = A + (size_t)(m0 + lrow) * K + lcol;
    const float* Wp = W + (size_t)(n0 + lrow) * K + lcol;

    // preload slab 0
    {
        float4 av = *(const float4*)Ap;
        float4 wv = *(const float4*)Wp;
        As[0][lcol + 0][lrow] = av.x; As[0][lcol + 1][lrow] = av.y;
        As[0][lcol + 2][lrow] = av.z; As[0][lcol + 3][lrow] = av.w;
        Bs[0][lcol + 0][lrow] = wv.x; Bs[0][lcol + 1][lrow] = wv.y;
        Bs[0][lcol + 2][lrow] = wv.z; Bs[0][lcol + 3][lrow] = wv.w;
    }
    __syncthreads();

    int nslab = K >> 3;
    for (int sI = 0; sI < nslab; sI++) {
        int cur = sI & 1;
        float4 av2, wv2;
        bool more = (sI + 1 < nslab);
        if (more) {
            av2 = *(const float4*)(Ap + (sI + 1) * 8);
            wv2 = *(const float4*)(Wp + (sI + 1) * 8);
        }
#pragma unroll
        for (int kk = 0; kk < 8; kk++) {
            float a[8];
            *(float4*)&a[0] = *(const float4*)&As[cur][kk][tr * 8];
            *(float4*)&a[4] = *(const float4*)&As[cur][kk][tr * 8 + 4];
            ulonglong2 bp0 = *(const ulonglong2*)&Bs[cur][kk][tc * 8];
            ulonglong2 bp1 = *(const ulonglong2*)&Bs[cur][kk][tc * 8 + 4];
#pragma unroll
            for (int i = 0; i < 8; i++) {
                ull ad = pk2(a[i], a[i]);
                fma2(acc[i][0], ad, bp0.x);
                fma2(acc[i][1], ad, bp0.y);
                fma2(acc[i][2], ad, bp1.x);
                fma2(acc[i][3], ad, bp1.y);
            }
        }
        if (more) {
            int nxt = cur ^ 1;
            As[nxt][lcol + 0][lrow] = av2.x; As[nxt][lcol + 1][lrow] = av2.y;
            As[nxt][lcol + 2][lrow] = av2.z; As[nxt][lcol + 3][lrow] = av2.w;
            Bs[nxt][lcol + 0][lrow] = wv2.x; Bs[nxt][lcol + 1][lrow] = wv2.y;
            Bs[nxt][lcol + 2][lrow] = wv2.z; Bs[nxt][lcol + 3][lrow] = wv2.w;
            __syncthreads();
        }
    }

    int nb = n0 + tc * 8;
    float bs[8];
#pragma unroll
    for (int j = 0; j < 8; j++) bs[j] = bias[nb + j];
#pragma unroll
    for (int i = 0; i < 8; i++) {
        int m = m0 + tr * 8 + i;
        float2 p0 = un2(acc[i][0]), p1 = un2(acc[i][1]);
        float2 p2 = un2(acc[i][2]), p3 = un2(acc[i][3]);
        float4 v0 = make_float4(p0.x + bs[0], p0.y + bs[1], p1.x + bs[2], p1.y + bs[3]);
        float4 v1 = make_float4(p2.x + bs[4], p2.y + bs[5], p3.x + bs[6], p3.y + bs[7]);
        *(float4*)&Gout[(size_t)m * NG + nb]     = v0;
        *(float4*)&Gout[(size_t)m * NG + nb + 4] = v1;
    }
}

// ---------------- persistent per-layer LSTM recurrence ------------------------
// grid = 128 CTAs (dir = bx>>6, 4 hidden units each), 256 threads.
// warp w, half=lane>>4, r=lane&15 = jj*4+g; thread does gate-row r for
// b = 2w+half+16*rep.  c in registers of g==0 lanes.  Per-direction barrier.
#define HS_STRIDE 260
__global__ __launch_bounds__(256) void lstm_layer_k(
    const float* __restrict__ G,
    const float* __restrict__ Whh0, const float* __restrict__ Whh1,
    float* __restrict__ y, unsigned bar_base)
{
    extern __shared__ float sm[];
    float* hs = sm;                       // [64][HS_STRIDE]
    float* ws = sm + 64 * HS_STRIDE;      // [16][HS_STRIDE]

    int bx  = blockIdx.x;
    int dir = bx >> 6;
    int j0  = (bx & 63) * 4;
    const float* Whh = dir ? Whh1 : Whh0;
    int tid  = threadIdx.x;
    int lane = tid & 31, w = tid >> 5;
    int half = lane >> 4, r = lane & 15;
    int jj = r >> 2, g = r & 3;
    int j  = j0 + jj;
    int bb0 = w * 2 + half;               // +16*rep

    // stage Whh rows once: row r=jj*4+g <- Whh[(g*256 + j0+jj)][:]
#pragma unroll
    for (int u = 0; u < 4; u++) {
        int f  = tid + u * 256;           // float4 index, 1024 total
        int rr = f >> 6;
        int kk = (f & 63) * 4;
        int gg = rr & 3, jq = rr >> 2;
        *(float4*)&ws[rr * HS_STRIDE + kk] =
            *(const float4*)&Whh[(size_t)(gg * 256 + j0 + jq) * HH + kk];
    }

    const float* wrow = &ws[r * HS_STRIDE];
    float cr0 = 0.f, cr1 = 0.f, cr2 = 0.f, cr3 = 0.f;
    volatile unsigned* vb = &g_bar2[dir];

    // prefetch input-projection gates for s = 0
    float a0, a1, a2, a3;
    {
        int t0 = dir ? (LL - 1) : 0;
        size_t gb = ((size_t)dir * LL + t0) * BB;
        size_t gof = (size_t)g * 256 + j;
        a0 = G[(gb + bb0 +  0) * NG + gof];
        a1 = G[(gb + bb0 + 16) * NG + gof];
        a2 = G[(gb + bb0 + 32) * NG + gof];
        a3 = G[(gb + bb0 + 48) * NG + gof];
    }

    for (int s = 0; s < LL; s++) {
        int t     = dir ? (LL - 1 - s) : s;
        int tprev = dir ? (t + 1) : (t - 1);

        if (s > 0) {
            // stage h_prev: warp iter i covers segment seg = i*8+w (128 x 512B)
            const float* ybase = y + ((size_t)tprev * BB) * HID + dir * HH;
#pragma unroll
            for (int i = 0; i < 16; i++) {
                int seg = i * 8 + w;
                int sb = seg >> 1, sh = (seg & 1) * 128;
                *(float4*)&hs[sb * HS_STRIDE + sh + lane * 4] =
                    *(const float4*)&ybase[(size_t)sb * HID + sh + lane * 4];
            }
            __syncthreads();

            const float* h0 = &hs[(bb0 +  0) * HS_STRIDE];
            const float* h1 = &hs[(bb0 + 16) * HS_STRIDE];
            const float* h2 = &hs[(bb0 + 32) * HS_STRIDE];
            const float* h3 = &hs[(bb0 + 48) * HS_STRIDE];
            ull c0a = pk2(0.f, 0.f), c0b = pk2(0.f, 0.f);
            ull c1a = pk2(0.f, 0.f), c1b = pk2(0.f, 0.f);
            ull c2a = pk2(0.f, 0.f), c2b = pk2(0.f, 0.f);
            ull c3a = pk2(0.f, 0.f), c3b = pk2(0.f, 0.f);
#pragma unroll 8
            for (int k = 0; k < HH; k += 4) {
                ulonglong2 wv = *(const ulonglong2*)&wrow[k];
                ulonglong2 u0 = *(const ulonglong2*)&h0[k];
                ulonglong2 u1 = *(const ulonglong2*)&h1[k];
                ulonglong2 u2 = *(const ulonglong2*)&h2[k];
                ulonglong2 u3 = *(const ulonglong2*)&h3[k];
                fma2(c0a, wv.x, u0.x); fma2(c0b, wv.y, u0.y);
                fma2(c1a, wv.x, u1.x); fma2(c1b, wv.y, u1.y);
                fma2(c2a, wv.x, u2.x); fma2(c2b, wv.y, u2.y);
                fma2(c3a, wv.x, u3.x); fma2(c3b, wv.y, u3.y);
            }
            a0 += red2(c0a) + red2(c0b);
            a1 += red2(c1a) + red2(c1b);
            a2 += red2(c2a) + red2(c2b);
            a3 += red2(c3a) + red2(c3b);
        } else {
            __syncthreads();
        }

        // combine gates i,f,g,o (lanes r = jj*4 + {0,1,2,3}) on g==0 lanes
        float f0 = __shfl_down_sync(0xffffffffu, a0, 1);
        float q0 = __shfl_down_sync(0xffffffffu, a0, 2);
        float o0 = __shfl_down_sync(0xffffffffu, a0, 3);
        float f1 = __shfl_down_sync(0xffffffffu, a1, 1);
        float q1 = __shfl_down_sync(0xffffffffu, a1, 2);
        float o1 = __shfl_down_sync(0xffffffffu, a1, 3);
        float f2 = __shfl_down_sync(0xffffffffu, a2, 1);
        float q2 = __shfl_down_sync(0xffffffffu, a2, 2);
        float o2 = __shfl_down_sync(0xffffffffu, a2, 3);
        float f3 = __shfl_down_sync(0xffffffffu, a3, 1);
        float q3 = __shfl_down_sync(0xffffffffu, a3, 2);
        float o3 = __shfl_down_sync(0xffffffffu, a3, 3);

        if (g == 0) {
            float* yt = y + ((size_t)t * BB) * HID + dir * HH + j;
            float ig, fg, gg2, og;
            ig = 1.f / (1.f + expf(-a0)); fg = 1.f / (1.f + expf(-f0));
            gg2 = tanhf(q0);              og = 1.f / (1.f + expf(-o0));
            cr0 = fg * cr0 + ig * gg2;
            yt[(size_t)(bb0 +  0) * HID] = og * tanhf(cr0);
            ig = 1.f / (1.f + expf(-a1)); fg = 1.f / (1.f + expf(-f1));
            gg2 = tanhf(q1);              og = 1.f / (1.f + expf(-o1));
            cr1 = fg * cr1 + ig * gg2;
            yt[(size_t)(bb0 + 16) * HID] = og * tanhf(cr1);
            ig = 1.f / (1.f + expf(-a2)); fg = 1.f / (1.f + expf(-f2));
            gg2 = tanhf(q2);              og = 1.f / (1.f + expf(-o2));
            cr2 = fg * cr2 + ig * gg2;
            yt[(size_t)(bb0 + 32) * HID] = og * tanhf(cr2);
            ig = 1.f / (1.f + expf(-a3)); fg = 1.f / (1.f + expf(-f3));
            gg2 = tanhf(q3);              og = 1.f / (1.f + expf(-o3));
            cr3 = fg * cr3 + ig * gg2;
            yt[(size_t)(bb0 + 48) * HID] = og * tanhf(cr3);
        }

        // prefetch gates for next step (hides DRAM latency behind the barrier)
        if (s + 1 < LL) {
            int tn = dir ? (LL - 2 - s) : (s + 1);
            size_t gb = ((size_t)dir * LL + tn) * BB;
            size_t gof = (size_t)g * 256 + j;
            a0 = G[(gb + bb0 +  0) * NG + gof];
            a1 = G[(gb + bb0 + 16) * NG + gof];
            a2 = G[(gb + bb0 + 32) * NG + gof];
            a3 = G[(gb + bb0 + 48) * NG + gof];
        }

        // per-direction grid barrier (64 CTAs)
        __threadfence();
        __syncthreads();
        if (tid == 0) {
            atomicAdd((unsigned*)&g_bar2[dir], 1u);
            unsigned target = bar_base + (unsigned)(s + 1) * 64u;
            while (*vb < target) __nanosleep(64);
        }
        __syncthreads();
        __threadfence();
    }
}

// ---------------- FC: emit[t][b][c] = feat[t][b][:]·Wfc[c] + bfc[c] -----------
__global__ void fc_k(const float* __restrict__ feat, const float* __restrict__ Wfc,
                     const float* __restrict__ bfc, float* __restrict__ emit)
{
    int gw = (int)(((size_t)blockIdx.x * blockDim.x + threadIdx.x) >> 5);
    int lane = threadIdx.x & 31;
    if (gw >= LL * BB) return;
    const float* f = feat + (size_t)gw * HID;
    float acc[CC] = {0.f, 0.f, 0.f, 0.f, 0.f};
#pragma unroll
    for (int i = 0; i < HID / 32; i++) {
        int k = lane + i * 32;
        float fv = f[k];
#pragma unroll
        for (int cc = 0; cc < CC; cc++) acc[cc] += fv * Wfc[cc * HID + k];
    }
#pragma unroll
    for (int off = 16; off > 0; off >>= 1)
#pragma unroll
        for (int cc = 0; cc < CC; cc++)
            acc[cc] += __shfl_down_sync(0xffffffffu, acc[cc], off);
    if (lane == 0)
#pragma unroll
        for (int cc = 0; cc < CC; cc++)
            emit[(size_t)gw * CC + cc] = acc[cc] + bfc[cc];
}

// ---------------- Viterbi + backtrace, one warp per batch element -------------
__global__ void viterbi_k(const float* __restrict__ emit, const float* __restrict__ trans,
                          int* __restrict__ bp, float* __restrict__ out, long long osz)
{
    int b = blockIdx.x;
    int lane = threadIdx.x;
    float tr[CC];
    if (lane < CC)
#pragma unroll
        for (int f = 0; f < CC; f++) tr[f] = trans[lane * CC + f];
    float score = (lane == TAG_START) ? 0.f : IMPOSSIBLE_F;

    for (int t = 0; t < LL; t++) {
        float sc[CC];
#pragma unroll
        for (int f = 0; f < CC; f++) sc[f] = __shfl_sync(0xffffffffu, score, f);
        if (lane < CC) {
            float best = sc[0] + tr[0];
            int arg = 0;
#pragma unroll
            for (int f = 1; f < CC; f++) {
                float v = sc[f] + tr[f];
                if (v > best) { best = v; arg = f; }
            }
            bp[((size_t)t * BB + b) * CC + lane] = arg;
            score = best + emit[((size_t)t * BB + b) * CC + lane];
        }
    }
    if (lane < CC) score += trans[TAG_STOP * CC + lane];
    float sc[CC];
#pragma unroll
    for (int f = 0; f < CC; f++) sc[f] = __shfl_sync(0xffffffffu, score, f);
    if (lane == 0) {
        float best = sc[0];
        int tag = 0;
#pragma unroll
        for (int f = 1; f < CC; f++)
            if (sc[f] > best) { best = sc[f]; tag = f; }
        if (b < osz) out[b] = best;                                   // best_score
        long long tb = 64;                                            // tag_seq base
        long long o = tb + (long long)b * LL + (LL - 1);
        if (o < osz) out[o] = (float)tag;
        for (int t = LL - 1; t >= 1; t--) {
            tag = bp[((size_t)t * BB + b) * CC + tag];
            o = tb + (long long)b * LL + (t - 1);
            if (o < osz) out[o] = (float)tag;
        }
    }
}

// ---------------- features [t][b][k] -> out [b][t][k] -------------------------
__global__ void feat_out_k(const float* __restrict__ feat, float* __restrict__ out,
                           long long osz)
{
    size_t i = (size_t)blockIdx.x * blockDim.x + threadIdx.x;   // float4 units
    size_t total = (size_t)LL * BB * HID / 4;
    if (i >= total) return;
    int k4 = (int)(i % (HID / 4));
    size_t p = i / (HID / 4);        // p = t*64 + b
    int b = (int)(p % BB);
    int t = (int)(p / BB);
    long long o = 32832LL + ((long long)b * LL + t) * HID + k4 * 4;
    if (o + 3 < osz)
        *(float4*)&out[o] = *(const float4*)&feat[p * HID + k4 * 4];
}

__global__ void mask_out_k(float* __restrict__ out, long long osz)
{
    long long i = (long long)blockIdx.x * blockDim.x + threadIdx.x;
    if (i >= (long long)BB * LL) return;
    long long o = 16810048LL + i;    // 64 + 32768 + 64*512*512
    if (o < osz) out[o] = 1.0f;      // all tokens > 0 => masks all True
}

// ---------------- launch -------------------------------------------------------
extern "C" void kernel_launch(void* const* d_in, const int* in_sizes, int n_in,
                              void* d_out, int out_size)
{
    const int*   xs    = (const int*)  d_in[0];
    const float* emb   = (const float*)d_in[1];
    const float* Wih0  = (const float*)d_in[2];   // [2,1024,256]
    const float* Whh0  = (const float*)d_in[3];   // [2,1024,256]
    const float* b0    = (const float*)d_in[4];   // [2,1024]
    const float* WihL  = (const float*)d_in[5];   // [3,2,1024,512]
    const float* WhhL  = (const float*)d_in[6];   // [3,2,1024,256]
    const float* bL    = (const float*)d_in[7];   // [3,2,1024]
    const float* Wfc   = (const float*)d_in[8];   // [5,512]
    const float* bfc   = (const float*)d_in[9];   // [5]
    const float* trans = (const float*)d_in[10];  // [5,5]
    float* out = (float*)d_out;
    long long osz = out_size;

    float *pX, *pA, *pB, *pG, *pE;
    int* pBP;
    cudaGetSymbolAddress((void**)&pX,  g_embx);
    cudaGetSymbolAddress((void**)&pA,  g_bufA);
    cudaGetSymbolAddress((void**)&pB,  g_bufB);
    cudaGetSymbolAddress((void**)&pG,  g_gates);
    cudaGetSymbolAddress((void**)&pE,  g_emit);
    cudaGetSymbolAddress((void**)&pBP, g_bp);

    const int STEP_SMEM = (64 + 16) * HS_STRIDE * 4;   // 83200 bytes
    cudaFuncSetAttribute(lstm_layer_k, cudaFuncAttributeMaxDynamicSharedMemorySize,
                         STEP_SMEM);

    init_bar_k<<<1, 32>>>();

    {
        size_t total = (size_t)LL * BB * (EE / 4);
        embed_k<<<(unsigned)((total + 255) / 256), 256>>>(xs, emb, pX);
    }

    const float* x = pX;
    int K = EE;
    for (int l = 0; l < 4; l++) {
        const float *WihF, *WihB, *WhhF, *WhhB, *bF, *bBk;
        if (l == 0) {
            WihF = Wih0;                 WihB = Wih0 + (size_t)NG * EE;
            WhhF = Whh0;                 WhhB = Whh0 + (size_t)NG * HH;
            bF   = b0;                   bBk  = b0 + NG;
        } else {
            size_t base = (size_t)(l - 1) * 2;
            WihF = WihL + base * NG * HID;       WihB = WihL + (base + 1) * NG * HID;
            WhhF = WhhL + base * NG * HH;        WhhB = WhhL + (base + 1) * NG * HH;
            bF   = bL + base * NG;               bBk  = bL + (base + 1) * NG;
        }
        float* y = (l & 1) ? pB : pA;

        dim3 ggrid(LL * BB / 128, NG / 128, 2);
        gemm_in_k<<<ggrid, 256>>>(x, WihF, WihB, bF, bBk, pG, K);

        lstm_layer_k<<<128, 256, STEP_SMEM>>>(pG, WhhF, WhhB, y,
                                              (unsigned)(l * LL * 64));

        x = y;
        K = HID;
    }

    // x == pB (final features, [t][b][512])
    fc_k<<<(LL * BB * 32) / 256, 256>>>(x, Wfc, bfc, pE);
    viterbi_k<<<BB, 32>>>(pE, trans, pBP, out, osz);
    {
        size_t total = (size_t)LL * BB * HID / 4;
        feat_out_k<<<(unsigned)((total + 255) / 256), 256>>>(x, out, osz);
    }
    mask_out_k<<<(BB * LL + 255) / 256, 256>>>(out, osz);
}

// round 5
// speedup vs baseline: 2.1117x; 1.1868x over previous
#include <cuda_runtime.h>
#include <math.h>
#include <stdint.h>
#include <mma.h>

using namespace nvcuda;

#define LL 512
#define BB 64
#define EE 256
#define HH 256
#define HID 512
#define NG 1024      // 4*H gate rows
#define CC 5
#define TAG_START 3
#define TAG_STOP 4
#define IMPOSSIBLE_F (-1e4f)

typedef unsigned long long ull;

// ---------------- packed fp32x2 FMA helpers (SASS FFMA2, PTX-only) ------------
__device__ __forceinline__ void fma2(ull& acc, ull a, ull b) {
    asm("fma.rn.f32x2 %0, %1, %2, %0;" : "+l"(acc) : "l"(a), "l"(b));
}
__device__ __forceinline__ ull pk2(float x, float y) {
    ull r; asm("mov.b64 %0, {%1, %2};" : "=l"(r) : "f"(x), "f"(y)); return r;
}
__device__ __forceinline__ float red2(ull v) {
    float x, y; asm("mov.b64 {%0, %1}, %2;" : "=f"(x), "=f"(y) : "l"(v)); return x + y;
}
__device__ __forceinline__ float tf32r(float x) {
    uint32_t u; asm("cvt.rna.tf32.f32 %0, %1;" : "=r"(u) : "f"(x));
    return __uint_as_float(u);
}

// ---------------- scratch (device globals; no cudaMalloc allowed) -------------
__device__ float g_embx [(size_t)LL * BB * EE];
__device__ float g_bufA [(size_t)LL * BB * HID];
__device__ float g_bufB [(size_t)LL * BB * HID];
__device__ float g_gates[(size_t)2 * LL * BB * NG];
__device__ float g_emit [(size_t)LL * BB * CC];
__device__ int   g_bp   [(size_t)LL * BB * CC];
__device__ unsigned g_bar2[2];

__global__ void init_bar_k() { if (threadIdx.x < 2) g_bar2[threadIdx.x] = 0u; }

// ---------------- embedding gather --------------------------------------------
__global__ void embed_k(const int* __restrict__ xs, const float* __restrict__ emb,
                        float* __restrict__ X)
{
    size_t i = (size_t)blockIdx.x * blockDim.x + threadIdx.x;
    size_t total = (size_t)LL * BB * (EE / 4);
    if (i >= total) return;
    int e4 = (int)(i % (EE / 4));
    size_t p = i / (EE / 4);
    int b = (int)(p % BB);
    int t = (int)(p / BB);
    int tok = xs[(size_t)b * LL + t];
    *(float4*)&X[p * EE + e4 * 4] = *(const float4*)&emb[(size_t)tok * EE + e4 * 4];
}

// ---------------- wmma tf32 input-projection GEMM -----------------------------
// G[dir][m][n] = A[m,:]·W[dir][n,:] + bias[n]
// CTA tile M=128 x N=128, K-chunks of 32, 8 warps (2m x 4n), warp tile 64x32.
// smem: 4 staging buffers of 128x36 f32 (A0,A1,W0,W1) = 73728 B; epilogue reuses.
#define GP 36                              // padded row stride (floats)
#define GBUF (128 * GP)                    // 4608 floats per buffer
#define GSM_TOT (4 * GBUF * 4)             // 73728 bytes

__global__ __launch_bounds__(256) void gemm_wmma_k(
    const float* __restrict__ A,
    const float* __restrict__ W0, const float* __restrict__ W1,
    const float* __restrict__ bias0, const float* __restrict__ bias1,
    float* __restrict__ G, int K)
{
    extern __shared__ float sm[];
    float* Abuf[2] = { sm,             sm + GBUF     };
    float* Wbuf[2] = { sm + 2 * GBUF,  sm + 3 * GBUF };

    int tid = threadIdx.x, wid = tid >> 5, lane = tid & 31;
    int m0 = blockIdx.x * 128;
    int n0 = blockIdx.y * 128;
    int dir = blockIdx.z;
    const float* W    = dir ? W1 : W0;
    const float* bias = dir ? bias1 : bias0;
    float* Gout = G + (size_t)dir * (LL * BB) * NG;

    int wm = wid >> 2;            // 0..1  (64 rows each)
    int wn = wid & 3;             // 0..3  (32 cols each)

    wmma::fragment<wmma::accumulator, 16, 16, 8, float> acc[4][2];
#pragma unroll
    for (int i = 0; i < 4; i++)
#pragma unroll
        for (int j = 0; j < 2; j++) wmma::fill_fragment(acc[i][j], 0.f);

    auto stage = [&](int c, int buf) {
        const float* Asrc = A + (size_t)m0 * K + c * 32;
        const float* Wsrc = W + (size_t)n0 * K + c * 32;
        float* ad = Abuf[buf];
        float* wd = Wbuf[buf];
#pragma unroll
        for (int u = 0; u < 4; u++) {
            int idx = tid + u * 256;      // 1024 float4 per matrix
            int row = idx >> 3, c4 = idx & 7;
            float4 v = *(const float4*)&Asrc[(size_t)row * K + c4 * 4];
            v.x = tf32r(v.x); v.y = tf32r(v.y); v.z = tf32r(v.z); v.w = tf32r(v.w);
            *(float4*)&ad[row * GP + c4 * 4] = v;
            float4 q = *(const float4*)&Wsrc[(size_t)row * K + c4 * 4];
            q.x = tf32r(q.x); q.y = tf32r(q.y); q.z = tf32r(q.z); q.w = tf32r(q.w);
            *(float4*)&wd[row * GP + c4 * 4] = q;
        }
    };

    stage(0, 0);
    __syncthreads();

    const int NC = K >> 5;
    for (int c = 0; c < NC; c++) {
        int cur = c & 1;
        if (c + 1 < NC) stage(c + 1, cur ^ 1);

        const float* ab = Abuf[cur] + wm * 64 * GP;
        const float* wb = Wbuf[cur] + wn * 32 * GP;
#pragma unroll
        for (int kk = 0; kk < 4; kk++) {
            wmma::fragment<wmma::matrix_a, 16, 16, 8, wmma::precision::tf32,
                           wmma::row_major> af[4];
            wmma::fragment<wmma::matrix_b, 16, 16, 8, wmma::precision::tf32,
                           wmma::col_major> bf[2];
#pragma unroll
            for (int i = 0; i < 4; i++)
                wmma::load_matrix_sync(af[i], ab + i * 16 * GP + kk * 8, GP);
#pragma unroll
            for (int j = 0; j < 2; j++)
                wmma::load_matrix_sync(bf[j], wb + j * 16 * GP + kk * 8, GP);
#pragma unroll
            for (int i = 0; i < 4; i++)
#pragma unroll
                for (int j = 0; j < 2; j++)
                    wmma::mma_sync(acc[i][j], af[i], bf[j], acc[i][j]);
        }
        __syncthreads();
    }

    // epilogue: frags -> smem (per-warp 64x36 region), + bias -> global
    float* eb = sm + wid * (64 * GP);
#pragma unroll
    for (int i = 0; i < 4; i++)
#pragma unroll
        for (int j = 0; j < 2; j++)
            wmma::store_matrix_sync(eb + i * 16 * GP + j * 16, acc[i][j], GP,
                                    wmma::mem_row_major);
    __syncwarp();

    int nb = n0 + wn * 32;
    float4 b4[8];
#pragma unroll
    for (int q = 0; q < 8; q++) b4[q] = *(const float4*)&bias[nb + q * 4];

#pragma unroll
    for (int rr = 0; rr < 2; rr++) {
        int row = lane + rr * 32;                     // 0..63
        const float* src = eb + row * GP;
        float* dst = &Gout[(size_t)(m0 + wm * 64 + row) * NG + nb];
#pragma unroll
        for (int q = 0; q < 8; q++) {
            float4 v = *(const float4*)&src[q * 4];
            v.x += b4[q].x; v.y += b4[q].y; v.z += b4[q].z; v.w += b4[q].w;
            *(float4*)&dst[q * 4] = v;
        }
    }
}

// ---------------- persistent per-layer LSTM recurrence ------------------------
#define HS_STRIDE 260
__global__ __launch_bounds__(256) void lstm_layer_k(
    const float* __restrict__ G,
    const float* __restrict__ Whh0, const float* __restrict__ Whh1,
    float* __restrict__ y, unsigned bar_base)
{
    extern __shared__ float sm[];
    float* hs = sm;                       // [64][HS_STRIDE]
    float* ws = sm + 64 * HS_STRIDE;      // [16][HS_STRIDE]

    int bx  = blockIdx.x;
    int dir = bx >> 6;
    int j0  = (bx & 63) * 4;
    const float* Whh = dir ? Whh1 : Whh0;
    int tid  = threadIdx.x;
    int lane = tid & 31, w = tid >> 5;
    int half = lane >> 4, r = lane & 15;
    int jj = r >> 2, g = r & 3;
    int j  = j0 + jj;
    int bb0 = w * 2 + half;

#pragma unroll
    for (int u = 0; u < 4; u++) {
        int f  = tid + u * 256;
        int rr = f >> 6;
        int kk = (f & 63) * 4;
        int gg = rr & 3, jq = rr >> 2;
        *(float4*)&ws[rr * HS_STRIDE + kk] =
            *(const float4*)&Whh[(size_t)(gg * 256 + j0 + jq) * HH + kk];
    }

    const float* wrow = &ws[r * HS_STRIDE];
    float cr0 = 0.f, cr1 = 0.f, cr2 = 0.f, cr3 = 0.f;
    unsigned* ctr = &g_bar2[dir];

    float a0, a1, a2, a3;
    {
        int t0 = dir ? (LL - 1) : 0;
        size_t gb = ((size_t)dir * LL + t0) * BB;
        size_t gof = (size_t)g * 256 + j;
        a0 = G[(gb + bb0 +  0) * NG + gof];
        a1 = G[(gb + bb0 + 16) * NG + gof];
        a2 = G[(gb + bb0 + 32) * NG + gof];
        a3 = G[(gb + bb0 + 48) * NG + gof];
    }

    for (int s = 0; s < LL; s++) {
        int t     = dir ? (LL - 1 - s) : s;
        int tprev = dir ? (t + 1) : (t - 1);

        if (s > 0) {
            const float* ybase = y + ((size_t)tprev * BB) * HID + dir * HH;
#pragma unroll
            for (int i = 0; i < 16; i++) {
                int seg = i * 8 + w;
                int sb2 = seg >> 1, sh = (seg & 1) * 128;
                *(float4*)&hs[sb2 * HS_STRIDE + sh + lane * 4] =
                    *(const float4*)&ybase[(size_t)sb2 * HID + sh + lane * 4];
            }
            __syncthreads();

            const float* h0 = &hs[(bb0 +  0) * HS_STRIDE];
            const float* h1 = &hs[(bb0 + 16) * HS_STRIDE];
            const float* h2 = &hs[(bb0 + 32) * HS_STRIDE];
            const float* h3 = &hs[(bb0 + 48) * HS_STRIDE];
            ull c0a = pk2(0.f, 0.f), c0b = pk2(0.f, 0.f);
            ull c1a = pk2(0.f, 0.f), c1b = pk2(0.f, 0.f);
            ull c2a = pk2(0.f, 0.f), c2b = pk2(0.f, 0.f);
            ull c3a = pk2(0.f, 0.f), c3b = pk2(0.f, 0.f);
#pragma unroll 8
            for (int k = 0; k < HH; k += 4) {
                ulonglong2 wv = *(const ulonglong2*)&wrow[k];
                ulonglong2 u0 = *(const ulonglong2*)&h0[k];
                ulonglong2 u1 = *(const ulonglong2*)&h1[k];
                ulonglong2 u2 = *(const ulonglong2*)&h2[k];
                ulonglong2 u3 = *(const ulonglong2*)&h3[k];
                fma2(c0a, wv.x, u0.x); fma2(c0b, wv.y, u0.y);
                fma2(c1a, wv.x, u1.x); fma2(c1b, wv.y, u1.y);
                fma2(c2a, wv.x, u2.x); fma2(c2b, wv.y, u2.y);
                fma2(c3a, wv.x, u3.x); fma2(c3b, wv.y, u3.y);
            }
            a0 += red2(c0a) + red2(c0b);
            a1 += red2(c1a) + red2(c1b);
            a2 += red2(c2a) + red2(c2b);
            a3 += red2(c3a) + red2(c3b);
        } else {
            __syncthreads();
        }

        float f0 = __shfl_down_sync(0xffffffffu, a0, 1);
        float q0 = __shfl_down_sync(0xffffffffu, a0, 2);
        float o0 = __shfl_down_sync(0xffffffffu, a0, 3);
        float f1 = __shfl_down_sync(0xffffffffu, a1, 1);
        float q1 = __shfl_down_sync(0xffffffffu, a1, 2);
        float o1 = __shfl_down_sync(0xffffffffu, a1, 3);
        float f2 = __shfl_down_sync(0xffffffffu, a2, 1);
        float q2 = __shfl_down_sync(0xffffffffu, a2, 2);
        float o2 = __shfl_down_sync(0xffffffffu, a2, 3);
        float f3 = __shfl_down_sync(0xffffffffu, a3, 1);
        float q3 = __shfl_down_sync(0xffffffffu, a3, 2);
        float o3 = __shfl_down_sync(0xffffffffu, a3, 3);

        if (g == 0) {
            float* yt = y + ((size_t)t * BB) * HID + dir * HH + j;
            float ig, fg, gg2, og;
            ig = 1.f / (1.f + expf(-a0)); fg = 1.f / (1.f + expf(-f0));
            gg2 = tanhf(q0);              og = 1.f / (1.f + expf(-o0));
            cr0 = fg * cr0 + ig * gg2;
            yt[(size_t)(bb0 +  0) * HID] = og * tanhf(cr0);
            ig = 1.f / (1.f + expf(-a1)); fg = 1.f / (1.f + expf(-f1));
            gg2 = tanhf(q1);              og = 1.f / (1.f + expf(-o1));
            cr1 = fg * cr1 + ig * gg2;
            yt[(size_t)(bb0 + 16) * HID] = og * tanhf(cr1);
            ig = 1.f / (1.f + expf(-a2)); fg = 1.f / (1.f + expf(-f2));
            gg2 = tanhf(q2);              og = 1.f / (1.f + expf(-o2));
            cr2 = fg * cr2 + ig * gg2;
            yt[(size_t)(bb0 + 32) * HID] = og * tanhf(cr2);
            ig = 1.f / (1.f + expf(-a3)); fg = 1.f / (1.f + expf(-f3));
            gg2 = tanhf(q3);              og = 1.f / (1.f + expf(-o3));
            cr3 = fg * cr3 + ig * gg2;
            yt[(size_t)(bb0 + 48) * HID] = og * tanhf(cr3);
        }

        if (s + 1 < LL) {
            int tn = dir ? (LL - 2 - s) : (s + 1);
            size_t gb = ((size_t)dir * LL + tn) * BB;
            size_t gof = (size_t)g * 256 + j;
            a0 = G[(gb + bb0 +  0) * NG + gof];
            a1 = G[(gb + bb0 + 16) * NG + gof];
            a2 = G[(gb + bb0 + 32) * NG + gof];
            a3 = G[(gb + bb0 + 48) * NG + gof];
        }

        // grid barrier (per direction, release/acquire)
        __syncthreads();
        if (tid == 0) {
            asm volatile("red.release.gpu.global.add.u32 [%0], %1;"
                         :: "l"(ctr), "r"(1u) : "memory");
            unsigned target = bar_base + (unsigned)(s + 1) * 64u;
            unsigned v;
            do {
                asm volatile("ld.acquire.gpu.global.u32 %0, [%1];"
                             : "=r"(v) : "l"(ctr) : "memory");
            } while (v < target);
        }
        __syncthreads();
    }
}

// ---------------- FC -----------------------------------------------------------
__global__ void fc_k(const float* __restrict__ feat, const float* __restrict__ Wfc,
                     const float* __restrict__ bfc, float* __restrict__ emit)
{
    int gw = (int)(((size_t)blockIdx.x * blockDim.x + threadIdx.x) >> 5);
    int lane = threadIdx.x & 31;
    if (gw >= LL * BB) return;
    const float* f = feat + (size_t)gw * HID;
    float acc[CC] = {0.f, 0.f, 0.f, 0.f, 0.f};
#pragma unroll
    for (int i = 0; i < HID / 32; i++) {
        int k = lane + i * 32;
        float fv = f[k];
#pragma unroll
        for (int cc = 0; cc < CC; cc++) acc[cc] += fv * Wfc[cc * HID + k];
    }
#pragma unroll
    for (int off = 16; off > 0; off >>= 1)
#pragma unroll
        for (int cc = 0; cc < CC; cc++)
            acc[cc] += __shfl_down_sync(0xffffffffu, acc[cc], off);
    if (lane == 0)
#pragma unroll
        for (int cc = 0; cc < CC; cc++)
            emit[(size_t)gw * CC + cc] = acc[cc] + bfc[cc];
}

// ---------------- Viterbi + backtrace ------------------------------------------
__global__ void viterbi_k(const float* __restrict__ emit, const float* __restrict__ trans,
                          int* __restrict__ bp, float* __restrict__ out, long long osz)
{
    int b = blockIdx.x;
    int lane = threadIdx.x;
    float tr[CC];
    if (lane < CC)
#pragma unroll
        for (int f = 0; f < CC; f++) tr[f] = trans[lane * CC + f];
    float score = (lane == TAG_START) ? 0.f : IMPOSSIBLE_F;

    for (int t = 0; t < LL; t++) {
        float sc[CC];
#pragma unroll
        for (int f = 0; f < CC; f++) sc[f] = __shfl_sync(0xffffffffu, score, f);
        if (lane < CC) {
            float best = sc[0] + tr[0];
            int arg = 0;
#pragma unroll
            for (int f = 1; f < CC; f++) {
                float v = sc[f] + tr[f];
                if (v > best) { best = v; arg = f; }
            }
            bp[((size_t)t * BB + b) * CC + lane] = arg;
            score = best + emit[((size_t)t * BB + b) * CC + lane];
        }
    }
    if (lane < CC) score += trans[TAG_STOP * CC + lane];
    float sc[CC];
#pragma unroll
    for (int f = 0; f < CC; f++) sc[f] = __shfl_sync(0xffffffffu, score, f);
    if (lane == 0) {
        float best = sc[0];
        int tag = 0;
#pragma unroll
        for (int f = 1; f < CC; f++)
            if (sc[f] > best) { best = sc[f]; tag = f; }
        if (b < osz) out[b] = best;
        long long tb = 64;
        long long o = tb + (long long)b * LL + (LL - 1);
        if (o < osz) out[o] = (float)tag;
        for (int t = LL - 1; t >= 1; t--) {
            tag = bp[((size_t)t * BB + b) * CC + tag];
            o = tb + (long long)b * LL + (t - 1);
            if (o < osz) out[o] = (float)tag;
        }
    }
}

// ---------------- features [t][b][k] -> out [b][t][k] --------------------------
__global__ void feat_out_k(const float* __restrict__ feat, float* __restrict__ out,
                           long long osz)
{
    size_t i = (size_t)blockIdx.x * blockDim.x + threadIdx.x;
    size_t total = (size_t)LL * BB * HID / 4;
    if (i >= total) return;
    int k4 = (int)(i % (HID / 4));
    size_t p = i / (HID / 4);
    int b = (int)(p % BB);
    int t = (int)(p / BB);
    long long o = 32832LL + ((long long)b * LL + t) * HID + k4 * 4;
    if (o + 3 < osz)
        *(float4*)&out[o] = *(const float4*)&feat[p * HID + k4 * 4];
}

__global__ void mask_out_k(float* __restrict__ out, long long osz)
{
    long long i = (long long)blockIdx.x * blockDim.x + threadIdx.x;
    if (i >= (long long)BB * LL) return;
    long long o = 16810048LL + i;
    if (o < osz) out[o] = 1.0f;
}

// ---------------- launch --------------------------------------------------------
extern "C" void kernel_launch(void* const* d_in, const int* in_sizes, int n_in,
                              void* d_out, int out_size)
{
    const int*   xs    = (const int*)  d_in[0];
    const float* emb   = (const float*)d_in[1];
    const float* Wih0  = (const float*)d_in[2];
    const float* Whh0  = (const float*)d_in[3];
    const float* b0    = (const float*)d_in[4];
    const float* WihL  = (const float*)d_in[5];
    const float* WhhL  = (const float*)d_in[6];
    const float* bL    = (const float*)d_in[7];
    const float* Wfc   = (const float*)d_in[8];
    const float* bfc   = (const float*)d_in[9];
    const float* trans = (const float*)d_in[10];
    float* out = (float*)d_out;
    long long osz = out_size;

    float *pX, *pA, *pB, *pG, *pE;
    int* pBP;
    cudaGetSymbolAddress((void**)&pX,  g_embx);
    cudaGetSymbolAddress((void**)&pA,  g_bufA);
    cudaGetSymbolAddress((void**)&pB,  g_bufB);
    cudaGetSymbolAddress((void**)&pG,  g_gates);
    cudaGetSymbolAddress((void**)&pE,  g_emit);
    cudaGetSymbolAddress((void**)&pBP, g_bp);

    const int STEP_SMEM = (64 + 16) * HS_STRIDE * 4;
    cudaFuncSetAttribute(lstm_layer_k, cudaFuncAttributeMaxDynamicSharedMemorySize,
                         STEP_SMEM);
    cudaFuncSetAttribute(gemm_wmma_k, cudaFuncAttributeMaxDynamicSharedMemorySize,
                         GSM_TOT);

    init_bar_k<<<1, 32>>>();

    {
        size_t total = (size_t)LL * BB * (EE / 4);
        embed_k<<<(unsigned)((total + 255) / 256), 256>>>(xs, emb, pX);
    }

    const float* x = pX;
    int K = EE;
    for (int l = 0; l < 4; l++) {
        const float *WihF, *WihB, *WhhF, *WhhB, *bF, *bBk;
        if (l == 0) {
            WihF = Wih0;                 WihB = Wih0 + (size_t)NG * EE;
            WhhF = Whh0;                 WhhB = Whh0 + (size_t)NG * HH;
            bF   = b0;                   bBk  = b0 + NG;
        } else {
            size_t base = (size_t)(l - 1) * 2;
            WihF = WihL + base * NG * HID;       WihB = WihL + (base + 1) * NG * HID;
            WhhF = WhhL + base * NG * HH;        WhhB = WhhL + (base + 1) * NG * HH;
            bF   = bL + base * NG;               bBk  = bL + (base + 1) * NG;
        }
        float* y = (l & 1) ? pB : pA;

        dim3 ggrid(LL * BB / 128, NG / 128, 2);
        gemm_wmma_k<<<ggrid, 256, GSM_TOT>>>(x, WihF, WihB, bF, bBk, pG, K);

        lstm_layer_k<<<128, 256, STEP_SMEM>>>(pG, WhhF, WhhB, y,
                                              (unsigned)(l * LL * 64));

        x = y;
        K = HID;
    }

    fc_k<<<(LL * BB * 32) / 256, 256>>>(x, Wfc, bfc, pE);
    viterbi_k<<<BB, 32>>>(pE, trans, pBP, out, osz);
    {
        size_t total = (size_t)LL * BB * HID / 4;
        feat_out_k<<<(unsigned)((total + 255) / 256), 256>>>(x, out, osz);
    }
    mask_out_k<<<(BB * LL + 255) / 256, 256>>>(out, osz);
}